// round 1
// baseline (speedup 1.0000x reference)
#include <cuda_runtime.h>

// seq2seq GRU encoder/decoder with attention, fp32 SIMT implementation.
// Shapes fixed by the problem: V=30000, E=256, H=512, B=64, S=64, max_len=32.

#define NB 64      // batch
#define NS 64      // encoder sequence length
#define NE 256     // embedding dim
#define NH 512     // hidden dim
#define NH3 1536   // 3*H
#define NV 30000   // vocab
#define NT 32      // max_len (decode steps)
#define KC 16      // K-chunk for smem-tiled GEMMs

// ---------------- device scratch (no allocation allowed) ----------------
__device__ float g_ex[NB * NS * NE];       // embedded encoder inputs
__device__ float g_gi[NB * NS * NH3];      // precomputed encoder input gates
__device__ float g_hA[NB * NH];            // hidden double buffer A
__device__ float g_hB[NB * NH];            // hidden double buffer B
__device__ float g_enc[NB * NS * NH];      // encoder outputs
__device__ float g_temp[NB * NS * NH];     // enc_outs @ attn_W.T + attn_b
__device__ float g_ctx[NB * NH];           // attention context
__device__ float g_demb[NB * NE];          // decoder input embedding
__device__ unsigned long long g_amax[NB];  // packed (value-key, ~index) argmax

__device__ __forceinline__ float sigf(float x) { return 1.0f / (1.0f + expf(-x)); }

// ---------------- embedding lookup for encoder inputs ----------------
__global__ __launch_bounds__(256) void k_embed(const int* __restrict__ x,
                                               const float* __restrict__ emb) {
    int i = blockIdx.x * 256 + threadIdx.x;   // grid covers exactly NB*NS*NE
    int bs = i >> 8;                          // / NE
    int e = i & 255;
    g_ex[i] = emb[x[bs] * NE + e];
}

__global__ __launch_bounds__(256) void k_zero_h() {
    int i = blockIdx.x * 256 + threadIdx.x;
    if (i < NB * NH) g_hA[i] = 0.0f;
}

// ---------------- generic 64x64-tile SGEMM: C = A @ W^T + bias ----------------
// sel==0: A=g_ex (M=4096,K), C=g_gi     (encoder input gates)
// sel==1: A=g_enc (M=4096,K), C=g_temp  (attention projection)
__global__ __launch_bounds__(256) void k_sgemm64(int sel, const float* __restrict__ W,
                                                 const float* __restrict__ bias,
                                                 int N, int K) {
    const float* A = sel ? g_enc : g_ex;
    float* C = sel ? g_temp : g_gi;
    __shared__ __align__(16) float As[KC][68];  // [k][m], padded
    __shared__ __align__(16) float Ws[KC][68];  // [k][n], padded
    int tid = threadIdx.x;
    int tx = tid & 15, ty = tid >> 4;
    int m0 = blockIdx.y * 64, n0 = blockIdx.x * 64;
    int lr = tid >> 2, lk = (tid & 3) * 4;
    float acc[4][4] = {};
    for (int k0 = 0; k0 < K; k0 += KC) {
        float4 av = *(const float4*)&A[(m0 + lr) * K + k0 + lk];
        float4 wv = *(const float4*)&W[(n0 + lr) * K + k0 + lk];
        __syncthreads();
        As[lk + 0][lr] = av.x; As[lk + 1][lr] = av.y; As[lk + 2][lr] = av.z; As[lk + 3][lr] = av.w;
        Ws[lk + 0][lr] = wv.x; Ws[lk + 1][lr] = wv.y; Ws[lk + 2][lr] = wv.z; Ws[lk + 3][lr] = wv.w;
        __syncthreads();
#pragma unroll
        for (int k = 0; k < KC; k++) {
            float4 a = *(const float4*)&As[k][tx * 4];
            float4 w = *(const float4*)&Ws[k][ty * 4];
            acc[0][0] += a.x * w.x; acc[0][1] += a.x * w.y; acc[0][2] += a.x * w.z; acc[0][3] += a.x * w.w;
            acc[1][0] += a.y * w.x; acc[1][1] += a.y * w.y; acc[1][2] += a.y * w.z; acc[1][3] += a.y * w.w;
            acc[2][0] += a.z * w.x; acc[2][1] += a.z * w.y; acc[2][2] += a.z * w.z; acc[2][3] += a.z * w.w;
            acc[3][0] += a.w * w.x; acc[3][1] += a.w * w.y; acc[3][2] += a.w * w.z; acc[3][3] += a.w * w.w;
        }
    }
#pragma unroll
    for (int i = 0; i < 4; i++) {
        int m = m0 + tx * 4 + i;
#pragma unroll
        for (int j = 0; j < 4; j++) {
            int n = n0 + ty * 4 + j;
            C[m * N + n] = acc[i][j] + bias[n];
        }
    }
}

// ---------------- one encoder GRU step ----------------
// Each block owns 4 hidden units (all 3 gate rows) for all 64 batch rows.
// Thread (b = tid&63, jj = tid>>6) accumulates all three gates for its unit,
// so the GRU nonlinearity needs no cross-thread exchange.
__global__ __launch_bounds__(256) void k_enc_step(const float* __restrict__ Whh,
                                                  const float* __restrict__ bhh,
                                                  int t, int swap) {
    const float* hin = swap ? g_hB : g_hA;
    float* hout = swap ? g_hA : g_hB;
    int j0 = blockIdx.x * 4;
    __shared__ __align__(16) float Hs[KC][68];  // [k][b]
    __shared__ float Ws[KC][16];                // [k][q], q = gate*4 + jj
    int tid = threadIdx.x;
    int b = tid & 63, jj = tid >> 6;
    int lr = tid >> 2, lk = (tid & 3) * 4;
    int wq = tid >> 4, wk = tid & 15;
    int wrow = (wq >> 2) * NH + j0 + (wq & 3);
    float a0 = 0.f, a1 = 0.f, a2 = 0.f;
    for (int k0 = 0; k0 < NH; k0 += KC) {
        float4 hv = *(const float4*)&hin[lr * NH + k0 + lk];
        float wv = 0.f;
        if (tid < 192) wv = Whh[wrow * NH + k0 + wk];
        __syncthreads();
        Hs[lk + 0][lr] = hv.x; Hs[lk + 1][lr] = hv.y; Hs[lk + 2][lr] = hv.z; Hs[lk + 3][lr] = hv.w;
        if (tid < 192) Ws[wk][wq] = wv;
        __syncthreads();
#pragma unroll
        for (int k = 0; k < KC; k++) {
            float hb = Hs[k][b];
            a0 += hb * Ws[k][jj];
            a1 += hb * Ws[k][4 + jj];
            a2 += hb * Ws[k][8 + jj];
        }
    }
    int j = j0 + jj;
    const float* gi = &g_gi[(b * NS + t) * NH3];  // already includes bih
    float r = sigf(gi[j] + a0 + bhh[j]);
    float z = sigf(gi[NH + j] + a1 + bhh[NH + j]);
    float n = tanhf(gi[2 * NH + j] + r * (a2 + bhh[2 * NH + j]));
    float hp = hin[b * NH + j];
    float hn = (1.0f - z) * n + z * hp;
    hout[b * NH + j] = hn;
    g_enc[(b * NS + t) * NH + j] = hn;
}

// ---------------- decoder init: context0 = h_enc, dec_emb0, argmax reset ----------------
__global__ __launch_bounds__(256) void k_dec_init(const int* __restrict__ sd,
                                                  const float* __restrict__ emb) {
    int b = blockIdx.x, tid = threadIdx.x;
    for (int k = tid; k < NH; k += 256) g_ctx[b * NH + k] = g_hA[b * NH + k];
    int idx = sd[b];
    for (int e = tid; e < NE; e += 256) g_demb[b * NE + e] = emb[idx * NE + e];
    if (tid == 0) g_amax[b] = 0ull;
}

// ---------------- one decoder GRU step (rnn_in = [dec_emb | context]) ----------------
__global__ __launch_bounds__(256) void k_dec_step(const float* __restrict__ Wih,
                                                  const float* __restrict__ Whh,
                                                  const float* __restrict__ bih,
                                                  const float* __restrict__ bhh,
                                                  int swap) {
    const float* hin = swap ? g_hB : g_hA;
    float* hout = swap ? g_hA : g_hB;
    int j0 = blockIdx.x * 4;
    __shared__ __align__(16) float Xs[KC][68];
    __shared__ float Ws[KC][16];
    int tid = threadIdx.x;
    int b = tid & 63, jj = tid >> 6;
    int lr = tid >> 2, lk = (tid & 3) * 4;
    int wq = tid >> 4, wk = tid & 15;
    int wrow = (wq >> 2) * NH + j0 + (wq & 3);
    float ai0 = 0.f, ai1 = 0.f, ai2 = 0.f;
    // phase 1: input gates over concatenated [dec_emb(256) | ctx(512)]
    for (int k0 = 0; k0 < NE + NH; k0 += KC) {
        const float* src = (k0 < NE) ? &g_demb[lr * NE + k0] : &g_ctx[lr * NH + (k0 - NE)];
        float4 xv = *(const float4*)&src[lk];
        float wv = 0.f;
        if (tid < 192) wv = Wih[wrow * (NE + NH) + k0 + wk];
        __syncthreads();
        Xs[lk + 0][lr] = xv.x; Xs[lk + 1][lr] = xv.y; Xs[lk + 2][lr] = xv.z; Xs[lk + 3][lr] = xv.w;
        if (tid < 192) Ws[wk][wq] = wv;
        __syncthreads();
#pragma unroll
        for (int k = 0; k < KC; k++) {
            float xb = Xs[k][b];
            ai0 += xb * Ws[k][jj];
            ai1 += xb * Ws[k][4 + jj];
            ai2 += xb * Ws[k][8 + jj];
        }
    }
    // phase 2: hidden gates
    float ah0 = 0.f, ah1 = 0.f, ah2 = 0.f;
    for (int k0 = 0; k0 < NH; k0 += KC) {
        float4 xv = *(const float4*)&hin[lr * NH + k0 + lk];
        float wv = 0.f;
        if (tid < 192) wv = Whh[wrow * NH + k0 + wk];
        __syncthreads();
        Xs[lk + 0][lr] = xv.x; Xs[lk + 1][lr] = xv.y; Xs[lk + 2][lr] = xv.z; Xs[lk + 3][lr] = xv.w;
        if (tid < 192) Ws[wk][wq] = wv;
        __syncthreads();
#pragma unroll
        for (int k = 0; k < KC; k++) {
            float xb = Xs[k][b];
            ah0 += xb * Ws[k][jj];
            ah1 += xb * Ws[k][4 + jj];
            ah2 += xb * Ws[k][8 + jj];
        }
    }
    int j = j0 + jj;
    float r = sigf(ai0 + bih[j] + ah0 + bhh[j]);
    float z = sigf(ai1 + bih[NH + j] + ah1 + bhh[NH + j]);
    float n = tanhf(ai2 + bih[2 * NH + j] + r * (ah2 + bhh[2 * NH + j]));
    float hp = hin[b * NH + j];
    hout[b * NH + j] = (1.0f - z) * n + z * hp;
}

// ---------------- fc logits + argmax: score = [h | ctx] @ fc_W^T + fc_b ----------------
// One block per 64-vocab tile, all 64 batch rows. Writes scores to d_out and
// accumulates the per-batch argmax via order-independent packed atomicMax.
__global__ __launch_bounds__(256) void k_fc(const float* __restrict__ fcW,
                                            const float* __restrict__ fcb,
                                            float* __restrict__ out,
                                            int step, int swap) {
    const float* h = swap ? g_hA : g_hB;  // matches k_dec_step's hout
    __shared__ __align__(16) float As[KC][68];
    __shared__ __align__(16) float Ws[KC][68];
    __shared__ unsigned long long best[64];
    int tid = threadIdx.x;
    int tx = tid & 15, ty = tid >> 4;
    if (tid < 64) best[tid] = 0ull;
    int v0 = blockIdx.x * 64;
    int lr = tid >> 2, lk = (tid & 3) * 4;
    float acc[4][4] = {};
    for (int k0 = 0; k0 < 2 * NH; k0 += KC) {
        const float* arow = (k0 < NH) ? &h[lr * NH + k0] : &g_ctx[lr * NH + (k0 - NH)];
        float4 av = *(const float4*)&arow[lk];
        int vr = v0 + lr;
        float4 wv = make_float4(0.f, 0.f, 0.f, 0.f);
        if (vr < NV) wv = *(const float4*)&fcW[vr * (2 * NH) + k0 + lk];
        __syncthreads();
        As[lk + 0][lr] = av.x; As[lk + 1][lr] = av.y; As[lk + 2][lr] = av.z; As[lk + 3][lr] = av.w;
        Ws[lk + 0][lr] = wv.x; Ws[lk + 1][lr] = wv.y; Ws[lk + 2][lr] = wv.z; Ws[lk + 3][lr] = wv.w;
        __syncthreads();
#pragma unroll
        for (int k = 0; k < KC; k++) {
            float4 a = *(const float4*)&As[k][tx * 4];
            float4 w = *(const float4*)&Ws[k][ty * 4];
            acc[0][0] += a.x * w.x; acc[0][1] += a.x * w.y; acc[0][2] += a.x * w.z; acc[0][3] += a.x * w.w;
            acc[1][0] += a.y * w.x; acc[1][1] += a.y * w.y; acc[1][2] += a.y * w.z; acc[1][3] += a.y * w.w;
            acc[2][0] += a.z * w.x; acc[2][1] += a.z * w.y; acc[2][2] += a.z * w.z; acc[2][3] += a.z * w.w;
            acc[3][0] += a.w * w.x; acc[3][1] += a.w * w.y; acc[3][2] += a.w * w.z; acc[3][3] += a.w * w.w;
        }
    }
#pragma unroll
    for (int i = 0; i < 4; i++) {
        int bb = tx * 4 + i;
        unsigned long long pk = 0ull;
#pragma unroll
        for (int j = 0; j < 4; j++) {
            int v = v0 + ty * 4 + j;
            if (v < NV) {
                float val = acc[i][j] + fcb[v];
                out[((long long)(bb * NT + step)) * NV + v] = val;
                unsigned u = __float_as_uint(val);
                u = (u & 0x80000000u) ? ~u : (u | 0x80000000u);
                unsigned long long p =
                    ((unsigned long long)u << 32) | (0xFFFFFFFFu - (unsigned)v);
                if (p > pk) pk = p;
            }
        }
        if (pk) atomicMax(&best[bb], pk);
    }
    __syncthreads();
    if (tid < 64) atomicMax(&g_amax[tid], best[tid]);
}

// ---------------- attention + next-token embedding + argmax reset ----------------
__global__ __launch_bounds__(256) void k_attn(const float* __restrict__ emb, int swap) {
    int b = blockIdx.x, tid = threadIdx.x;
    const float* h = swap ? g_hA : g_hB;
    __shared__ float hc[NH];
    __shared__ float sc[NS];
    for (int k = tid; k < NH; k += 256) hc[k] = h[b * NH + k];
    unsigned long long key = g_amax[b];  // all threads read before any reset
    int idx = (int)(0xFFFFFFFFu - (unsigned)(key & 0xFFFFFFFFull));
    for (int e = tid; e < NE; e += 256) g_demb[b * NE + e] = emb[idx * NE + e];
    __syncthreads();
    int w = tid >> 5, lane = tid & 31;
    for (int s = w; s < NS; s += 8) {
        const float* tp = &g_temp[(b * NS + s) * NH];
        float d = 0.f;
        for (int k = lane; k < NH; k += 32) d += tp[k] * hc[k];
#pragma unroll
        for (int off = 16; off; off >>= 1) d += __shfl_down_sync(0xFFFFFFFFu, d, off);
        if (lane == 0) sc[s] = d;
    }
    __syncthreads();
    if (tid == 0) {
        float m = sc[0];
        for (int s = 1; s < NS; s++) m = fmaxf(m, sc[s]);
        float sum = 0.f;
        for (int s = 0; s < NS; s++) { float e2 = expf(sc[s] - m); sc[s] = e2; sum += e2; }
        float inv = 1.0f / sum;
        for (int s = 0; s < NS; s++) sc[s] *= inv;
        g_amax[b] = 0ull;  // reset for next step's fc (safe: key read pre-sync)
    }
    __syncthreads();
    for (int hh = tid; hh < NH; hh += 256) {
        float c = 0.f;
        for (int s = 0; s < NS; s++) c += sc[s] * g_enc[(b * NS + s) * NH + hh];
        g_ctx[b * NH + hh] = c;
    }
}

// ---------------- launch ----------------
extern "C" void kernel_launch(void* const* d_in, const int* in_sizes, int n_in,
                              void* d_out, int out_size) {
    const int* x = (const int*)d_in[0];
    const int* sd = (const int*)d_in[1];
    // d_in[2] = max_len (fixed at 32)
    const float* emb = (const float*)d_in[3];
    const float* eWih = (const float*)d_in[4];
    const float* eWhh = (const float*)d_in[5];
    const float* ebih = (const float*)d_in[6];
    const float* ebhh = (const float*)d_in[7];
    const float* dWih = (const float*)d_in[8];
    const float* dWhh = (const float*)d_in[9];
    const float* dbih = (const float*)d_in[10];
    const float* dbhh = (const float*)d_in[11];
    const float* fcW = (const float*)d_in[12];
    const float* fcb = (const float*)d_in[13];
    const float* aW = (const float*)d_in[14];
    const float* ab = (const float*)d_in[15];
    float* out = (float*)d_out;

    // 1) embed encoder inputs + zero h0
    k_embed<<<(NB * NS * NE) / 256, 256>>>(x, emb);
    k_zero_h<<<(NB * NH + 255) / 256, 256>>>();

    // 2) precompute all encoder input gates: g_gi = ex @ enc_Wih^T + bih
    k_sgemm64<<<dim3(NH3 / 64, (NB * NS) / 64), 256>>>(0, eWih, ebih, NH3, NE);

    // 3) 64 sequential encoder GRU steps (double-buffered h; ends in g_hA)
    for (int t = 0; t < NS; t++)
        k_enc_step<<<NH / 4, 256>>>(eWhh, ebhh, t, t & 1);

    // 4) attention projection: g_temp = enc_outs @ attn_W^T + attn_b
    k_sgemm64<<<dim3(NH / 64, (NB * NS) / 64), 256>>>(1, aW, ab, NH, NH);

    // 5) decoder init: ctx = h_enc, dec_emb = emb[start_decode], argmax = 0
    k_dec_init<<<NB, 256>>>(sd, emb);

    // 6) 32 sequential decode steps: GRU -> fc(+argmax) -> attention(+gather)
    for (int d = 0; d < NT; d++) {
        int sw = d & 1;
        k_dec_step<<<NH / 4, 256>>>(dWih, dWhh, dbih, dbhh, sw);
        k_fc<<<(NV + 63) / 64, 256>>>(fcW, fcb, out, d, sw);
        k_attn<<<NB, 256>>>(emb, sw);
    }
}